// round 16
// baseline (speedup 1.0000x reference)
#include <cuda_runtime.h>
#include <cuda_fp16.h>
#include <cstdint>

#define NN    3072
#define HH    8
#define FF    64
#define OUTF  512
#define INF_  256
#define KT    64
#define NT    (NN / KT)     // 48
#define MI    96            // i rows per CTA in gat_tc
#define NW    (NN / 32)     // adj bitmask words per row
#define LOG2E 1.4426950408889634f

// ---- scratch (device globals) ----
__device__ float d_sl[NN * HH];           // pre-scaled by log2(e)
__device__ float d_sr[NN * HH];           // pre-scaled
__device__ float d_m[NN * HH];            // scaled row max
__device__ float d_Cc[NN * HH];           // any0 ? exp2(LOG2E - m) : 0
__device__ uint32_t d_adjbits[NN * NW];
__device__ __half d_gthi[HH * FF * NN];   // g^T fp16 (rn), j-permuted: [h][f][j']
__device__ __half d_xphi[NN * INF_];      // x split hi, k-permuted
__device__ __half d_xplo[NN * INF_];
__device__ __half d_wthi[OUTF * INF_];    // W^T split hi, k-permuted: [n][k']
__device__ __half d_wtlo[OUTF * INF_];

// permutation within 16-group: position p holds actual k = KTAB(p)
#define KTAB(pp) (2 * ((pp) >> 2) + (((pp) & 2) ? 8 : 0) + ((pp) & 1))

// select LUT: 2 mask bits -> byte_perm selector (e bytes 0-3, C bytes 4-7)
static constexpr uint64_t SELLUT = 0x3210325476107654ull;

// ---------------- helpers ----------------
__device__ __forceinline__ uint32_t smem_u32(const void* p) {
    uint32_t a;
    asm("{ .reg .u64 t; cvta.to.shared.u64 t, %1; cvt.u32.u64 %0, t; }" : "=r"(a) : "l"(p));
    return a;
}
__device__ __forceinline__ void cp16(void* dst, const void* src) {
    asm volatile("cp.async.cg.shared.global [%0], [%1], 16;\n" :: "r"(smem_u32(dst)), "l"(src));
}
__device__ __forceinline__ void cp4(void* dst, const void* src) {
    asm volatile("cp.async.ca.shared.global [%0], [%1], 4;\n" :: "r"(smem_u32(dst)), "l"(src));
}
#define CP_COMMIT() asm volatile("cp.async.commit_group;\n")
#define CP_WAIT(n)  asm volatile("cp.async.wait_group %0;\n" :: "n"(n))

__device__ __forceinline__ void mma16816(float* d, const uint32_t* a,
                                         uint32_t b0, uint32_t b1) {
    asm volatile(
        "mma.sync.aligned.m16n8k16.row.col.f32.f16.f16.f32 "
        "{%0,%1,%2,%3}, {%4,%5,%6,%7}, {%8,%9}, {%0,%1,%2,%3};"
        : "+f"(d[0]), "+f"(d[1]), "+f"(d[2]), "+f"(d[3])
        : "r"(a[0]), "r"(a[1]), "r"(a[2]), "r"(a[3]), "r"(b0), "r"(b1));
}
__device__ __forceinline__ uint32_t ph2(float lo, float hi) {
    __half2 h = __floats2half2_rn(lo, hi);
    return *(uint32_t*)&h;
}
__device__ __forceinline__ uint32_t ex2h2(uint32_t a) {
    uint32_t r;
    asm("ex2.approx.f16x2 %0, %1;" : "=r"(r) : "r"(a));
    return r;
}
__device__ __forceinline__ void split16(const float* v_strided, int stride,
                                        uint4* hi2, uint4* lo2) {
    uint32_t hw[8], lw[8];
    #pragma unroll
    for (int q = 0; q < 8; q++) {
        float v0 = v_strided[KTAB(2 * q) * stride];
        float v1 = v_strided[KTAB(2 * q + 1) * stride];
        __half h0 = __float2half_rn(v0), h1 = __float2half_rn(v1);
        float r0 = v0 - __half2float(h0), r1 = v1 - __half2float(h1);
        __half l0 = __float2half_rn(r0), l1 = __float2half_rn(r1);
        hw[q] = ((uint32_t)__half_as_ushort(h1) << 16) | __half_as_ushort(h0);
        lw[q] = ((uint32_t)__half_as_ushort(l1) << 16) | __half_as_ushort(l0);
    }
    hi2[0] = make_uint4(hw[0], hw[1], hw[2], hw[3]);
    hi2[1] = make_uint4(hw[4], hw[5], hw[6], hw[7]);
    lo2[0] = make_uint4(lw[0], lw[1], lw[2], lw[3]);
    lo2[1] = make_uint4(lw[4], lw[5], lw[6], lw[7]);
}

// ============================================================
// Kernel 0: prep = xsplit (blocks 0..191) + wsplit (blocks 192..223)
// ============================================================
__global__ void prep_kernel(const float* __restrict__ x, const float* __restrict__ W) {
    int t = threadIdx.x;
    if (blockIdx.x < 192) {
        __shared__ float s[16][257];
        int r0 = blockIdx.x * 16;
        #pragma unroll
        for (int q = 0; q < 4; q++) {
            int idx = t + q * 256;
            int r = idx >> 6, c4 = (idx & 63) * 4;
            float4 v = *(const float4*)(x + (size_t)(r0 + r) * INF_ + c4);
            s[r][c4] = v.x; s[r][c4 + 1] = v.y; s[r][c4 + 2] = v.z; s[r][c4 + 3] = v.w;
        }
        __syncthreads();
        int r = t >> 4, grp = (t & 15) * 16;
        uint4 hi2[2], lo2[2];
        split16(&s[r][grp], 1, hi2, lo2);
        uint4* dh = (uint4*)(d_xphi + (size_t)(r0 + r) * INF_ + grp);
        uint4* dl = (uint4*)(d_xplo + (size_t)(r0 + r) * INF_ + grp);
        dh[0] = hi2[0]; dh[1] = hi2[1];
        dl[0] = lo2[0]; dl[1] = lo2[1];
    } else {
        __shared__ float s[64][65];
        int b = blockIdx.x - 192;
        int k0 = (b & 3) * 64, n0 = (b >> 2) * 64;
        #pragma unroll
        for (int q = 0; q < 4; q++) {
            int idx = t + q * 256;
            int k = idx >> 4, n4 = (idx & 15) * 4;
            float4 v = *(const float4*)(W + (size_t)(k0 + k) * OUTF + n0 + n4);
            s[k][n4] = v.x; s[k][n4 + 1] = v.y; s[k][n4 + 2] = v.z; s[k][n4 + 3] = v.w;
        }
        __syncthreads();
        int n = t >> 2, grp = (t & 3) * 16;
        uint4 hi2[2], lo2[2];
        split16(&s[grp][n], 65, hi2, lo2);
        uint4* dh = (uint4*)(d_wthi + (size_t)(n0 + n) * INF_ + k0 + grp);
        uint4* dl = (uint4*)(d_wtlo + (size_t)(n0 + n) * INF_ + k0 + grp);
        dh[0] = hi2[0]; dh[1] = hi2[1];
        dl[0] = lo2[0]; dl[1] = lo2[1];
    }
}

// ============================================================
// Kernel 1: g = x @ W via HMMA (3-pass split), fused epilogue:
// scores (scaled) + g^T fp16 j-permuted. grid (48, 8), 128 thr.
// ============================================================
constexpr int BROW = 264;
constexpr int GEMM_SMEM = 2 * 64 * BROW * 2;    // 67584 B

__global__ void __launch_bounds__(128, 1) gemm_tc(const float* __restrict__ aw) {
    extern __shared__ char gsm[];
    __half* Bhi = (__half*)gsm;
    __half* Blo = Bhi + 64 * BROW;
    int t = threadIdx.x, lane = t & 31, w = t >> 5;
    int m0 = blockIdx.x * 64, h = blockIdx.y, n0 = h * FF;

    #pragma unroll
    for (int q = 0; q < 16; q++) {
        int idx = t + q * 128;
        int n = idx >> 5, c = idx & 31;
        cp16(Bhi + n * BROW + c * 8, d_wthi + (size_t)(n0 + n) * INF_ + c * 8);
        cp16(Blo + n * BROW + c * 8, d_wtlo + (size_t)(n0 + n) * INF_ + c * 8);
    }
    CP_COMMIT(); CP_WAIT(0);
    __syncthreads();

    int gid = lane >> 2, tig = lane & 3;
    const uint2* xh0 = (const uint2*)(d_xphi + (size_t)(m0 + w * 16 + gid) * INF_);
    const uint2* xh8 = (const uint2*)(d_xphi + (size_t)(m0 + w * 16 + gid + 8) * INF_);
    const uint2* xl0 = (const uint2*)(d_xplo + (size_t)(m0 + w * 16 + gid) * INF_);
    const uint2* xl8 = (const uint2*)(d_xplo + (size_t)(m0 + w * 16 + gid + 8) * INF_);

    float d[8][4] = {};
    #pragma unroll 4
    for (int s = 0; s < 16; s++) {
        uint2 ah0 = xh0[s * 4 + tig], ah8 = xh8[s * 4 + tig];
        uint2 al0 = xl0[s * 4 + tig], al8 = xl8[s * 4 + tig];
        uint32_t Ahi[4] = {ah0.x, ah8.x, ah0.y, ah8.y};
        uint32_t Alo[4] = {al0.x, al8.x, al0.y, al8.y};
        #pragma unroll
        for (int nt = 0; nt < 8; nt++) {
            int boff = (nt * 8 + gid) * BROW + s * 16 + 4 * tig;
            uint2 bh = *(const uint2*)(Bhi + boff);
            uint2 bl = *(const uint2*)(Blo + boff);
            mma16816(d[nt], Ahi, bh.x, bh.y);
            mma16816(d[nt], Ahi, bl.x, bl.y);
            mma16816(d[nt], Alo, bh.x, bh.y);
        }
    }
    __syncthreads();    // B dead; overlay transpose buffer

    float* trans = (float*)gsm;     // [64][66]
    int r1 = w * 16 + gid, r2 = r1 + 8;
    #pragma unroll
    for (int nt = 0; nt < 8; nt++) {
        int cc = nt * 8 + 2 * tig;
        trans[r1 * 66 + cc] = d[nt][0]; trans[r1 * 66 + cc + 1] = d[nt][1];
        trans[r2 * 66 + cc] = d[nt][2]; trans[r2 * 66 + cc + 1] = d[nt][3];
    }
    __syncthreads();

    // ---- fused scores (x log2e) ----
    {
        int r = t >> 1, half = t & 1;
        const float* row = trans + r * 66 + half * 32;
        const float* awl = aw + half * 32;
        const float* awr = aw + 64 + half * 32;
        float sl = 0.f, sr = 0.f;
        #pragma unroll
        for (int q = 0; q < 32; q++) {
            float gv = row[q];
            sl += gv * awl[q];
            sr += gv * awr[q];
        }
        sl += __shfl_xor_sync(0xffffffffu, sl, 1);
        sr += __shfl_xor_sync(0xffffffffu, sr, 1);
        if (!half) {
            d_sl[(m0 + r) * HH + h] = sl * LOG2E;
            d_sr[(m0 + r) * HH + h] = sr * LOG2E;
        }
    }

    // ---- g^T fp16 (hi only), j-permuted ----
    {
        int f = t >> 1, half = t & 1;
        #pragma unroll
        for (int jq = 0; jq < 2; jq++) {
            int p0 = 32 * half + jq * 16;
            uint32_t hw[8];
            #pragma unroll
            for (int q = 0; q < 8; q++) {
                float v0 = trans[(p0 + KTAB(2 * q)) * 66 + f];
                float v1 = trans[(p0 + KTAB(2 * q + 1)) * 66 + f];
                hw[q] = ph2(v0, v1);
            }
            uint4* dh = (uint4*)(d_gthi + ((size_t)h * FF + f) * NN + m0 + p0);
            dh[0] = make_uint4(hw[0], hw[1], hw[2], hw[3]);
            dh[1] = make_uint4(hw[4], hw[5], hw[6], hw[7]);
        }
    }
}

// ============================================================
// Kernel 2: per-row adj scan -> m[i,h] (scaled), C; packs adj bits
// (R13 version: 3072 CTAs, high occupancy hides ballot serialization)
// ============================================================
__global__ void rowc_kernel(const int* __restrict__ adj) {
    int i = blockIdx.x, t = threadIdx.x;
    float mx[8];
    #pragma unroll
    for (int h = 0; h < 8; h++) mx[h] = -3.0e38f;
    int any0 = 0;
    const int* ar = adj + (size_t)i * NN;
    for (int j = t; j < NN; j += 256) {
        int a = ar[j];
        uint32_t bal = __ballot_sync(0xffffffffu, a != 0);
        if ((t & 31) == 0) d_adjbits[i * NW + (j >> 5)] = bal;
        if (a) {
            const float4* p = (const float4*)(d_sr + j * HH);
            float4 v0 = p[0], v1 = p[1];
            mx[0] = fmaxf(mx[0], v0.x); mx[1] = fmaxf(mx[1], v0.y);
            mx[2] = fmaxf(mx[2], v0.z); mx[3] = fmaxf(mx[3], v0.w);
            mx[4] = fmaxf(mx[4], v1.x); mx[5] = fmaxf(mx[5], v1.y);
            mx[6] = fmaxf(mx[6], v1.z); mx[7] = fmaxf(mx[7], v1.w);
        } else any0 = 1;
    }
    __shared__ float wmax[8][8];
    __shared__ int s_any;
    if (t == 0) s_any = 0;
    __syncthreads();
    if (any0) s_any = 1;
    int lane = t & 31, wid = t >> 5;
    #pragma unroll
    for (int h = 0; h < 8; h++) {
        float v = mx[h];
        #pragma unroll
        for (int o = 16; o; o >>= 1) v = fmaxf(v, __shfl_down_sync(0xffffffffu, v, o));
        if (lane == 0) wmax[h][wid] = v;
    }
    __syncthreads();
    if (t < 8) {
        int h = t;
        float mradj = wmax[h][0];
        #pragma unroll
        for (int w = 1; w < 8; w++) mradj = fmaxf(mradj, wmax[h][w]);
        float sl = d_sl[i * HH + h];
        float s  = sl + mradj;
        float lk = fmaxf(s, 0.2f * s);
        float m  = s_any ? fmaxf(LOG2E, lk) : lk;
        d_m[i * HH + h]  = m;
        d_Cc[i * HH + h] = s_any ? exp2f(LOG2E - m) : 0.0f;
    }
}

// ============================================================
// Kernel 3: HMMA main. K-split + 2 CTAs/SM:
// 192 thr = 6 warps; warps 0-2 own all 96 rows (32/warp) for j[0:32),
// warps 3-5 same rows for j[32:64). B frag feeds 2 MMAs.
// grid 256 = 32 i-tiles x 8 heads -> 2 CTAs/SM (two sync domains).
// ============================================================
constexpr int BUF_BYTES = 64 * 80 * 2;              // 10240 per stage
constexpr int OFF_SR3   = 3 * BUF_BYTES;            // 30720
constexpr int SMEM_TC   = OFF_SR3 + 3 * 256;        // 31488
constexpr int OFF_ZS    = MI * 66 * 4;              // 25344 (inside stage-buf overlay)

__global__ void __launch_bounds__(192, 2) gat_tc(float* __restrict__ out) {
    extern __shared__ char smem[];

    int t = threadIdx.x, lane = t & 31, w = t >> 5;    // w 0..5
    int grp = (w >= 3);
    int mt = grp ? w - 3 : w;                          // 0..2
    int h = blockIdx.x & 7;
    int i0 = (blockIdx.x >> 3) * MI;
    int gid = lane >> 2, tig = lane & 3;
    int t2 = 2 * tig;
    int r0 = mt * 32 + gid;             // rows r0, +8, +16, +24

    // per-row constants (4 row-subblocks)
    float slm[4], cm[4];
    uint32_t C2[4];
    const uint32_t* ab[4];
    #pragma unroll
    for (int r = 0; r < 4; r++) {
        int gi = (i0 + r0 + r * 8) * HH + h;
        float m = d_m[gi];
        slm[r] = d_sl[gi] - m;
        cm[r]  = -0.8f * m;
        C2[r]  = ph2(d_Cc[gi], d_Cc[gi]);
        ab[r]  = d_adjbits + (size_t)(i0 + r0 + r * 8) * NW + grp;
    }

    // ---- hoisted staging descriptors (512 cp16 over 192 threads) ----
    const char* g_src[3];
    uint32_t g_dst[3];
    #pragma unroll
    for (int q = 0; q < 3; q++) {
        int idx = t + q * 192;
        if (idx < 512) {
            int f = idx >> 3, c = idx & 7;
            g_src[q] = (const char*)(d_gthi + ((size_t)h * FF + f) * NN + c * 8);
            g_dst[q] = (uint32_t)((f * 80 + c * 8) * 2);
        }
    }
    const char* s_src = nullptr;
    uint32_t s_dst = 0;
    if (t < 64) {
        int joff = (t & ~15) + KTAB(t & 15);
        s_src = (const char*)(d_sr + (size_t)joff * HH + h);
        s_dst = (uint32_t)(t * 4);
    }

    auto stage = [&](int bi) {
        uint32_t boff = bi * BUF_BYTES;
        cp16(smem + boff + g_dst[0], g_src[0]); g_src[0] += 64 * 2;
        cp16(smem + boff + g_dst[1], g_src[1]); g_src[1] += 64 * 2;
        if (t < 128) { cp16(smem + boff + g_dst[2], g_src[2]); g_src[2] += 64 * 2; }
        if (t < 64) {
            cp4(smem + OFF_SR3 + bi * 256 + s_dst, s_src);
            s_src += 64 * HH * 4;         // +64 j (floats, stride HH)
        }
    };

    float d0[8][4] = {}, d1[8][4] = {};
    float dz0[4] = {}, dz1[4] = {};
    uint32_t bz = (gid == 0) ? 0x3C003C00u : 0u;   // ones column (n=0)
    int sbase = grp * 2;

    stage(0); CP_COMMIT();
    stage(1); CP_COMMIT();
    int cur = 0, stg = 2;

    for (int jt = 0; jt < NT; ++jt) {
        if (jt < NT - 1) CP_WAIT(1); else CP_WAIT(0);
        __syncthreads();
        if (jt + 2 < NT) { stage(stg); CP_COMMIT(); stg = (stg == 2) ? 0 : stg + 1; }

        uint32_t bwv[4];
        #pragma unroll
        for (int r = 0; r < 4; r++) bwv[r] = ab[r][jt * 2];
        const float* srh = (const float*)(smem + OFF_SR3 + cur * 256);
        const __half* bb = (const __half*)(smem + cur * BUF_BYTES);

        #pragma unroll
        for (int ss = 0; ss < 2; ss++) {
            int s = sbase + ss;
            float4 sv = *(const float4*)(srh + s * 16 + 4 * tig);
            uint32_t A0[4], A1[4];
            #pragma unroll
            for (int r = 0; r < 4; r++) {
                uint32_t sh = bwv[r] >> ((ss << 4) + t2);
                float u0 = sv.x + slm[r], u1 = sv.y + slm[r];
                float u2 = sv.z + slm[r], u3 = sv.w + slm[r];
                float l0 = fmaxf(u0, fmaf(u0, 0.2f, cm[r]));
                float l1 = fmaxf(u1, fmaf(u1, 0.2f, cm[r]));
                float l2 = fmaxf(u2, fmaf(u2, 0.2f, cm[r]));
                float l3 = fmaxf(u3, fmaf(u3, 0.2f, cm[r]));
                uint32_t e01 = ex2h2(ph2(l0, l1));
                uint32_t e23 = ex2h2(ph2(l2, l3));
                uint32_t sel1 = (uint32_t)(SELLUT >> ((sh << 4) & 0x30));
                uint32_t sel2 = (uint32_t)(SELLUT >> ((sh >> 4) & 0x30));
                uint32_t wlo = __byte_perm(e01, C2[r], sel1);
                uint32_t whi = __byte_perm(e23, C2[r], sel2);
                if (r < 2) { A0[r] = wlo; A0[r + 2] = whi; }
                else       { A1[r - 2] = wlo; A1[r] = whi; }
            }
            mma16816(dz0, A0, bz, bz);
            mma16816(dz1, A1, bz, bz);
            #pragma unroll
            for (int nt = 0; nt < 8; nt++) {
                uint2 b = *(const uint2*)(bb + (nt * 8 + gid) * 80 + s * 16 + 4 * tig);
                mma16816(d0[nt], A0, b.x, b.y);
                mma16816(d1[nt], A1, b.x, b.y);
            }
        }
        cur = (cur == 2) ? 0 : cur + 1;
    }

    // ---- epilogue: merge K-half partials across warp groups via smem ----
    __syncthreads();                     // stage buffers dead; overlay
    float* red = (float*)smem;           // [96][66]
    float* zs  = (float*)(smem + OFF_ZS);// [96][2]
    if (tig == 0) {
        zs[(r0)      * 2 + grp] = dz0[0];
        zs[(r0 + 8)  * 2 + grp] = dz0[2];
        zs[(r0 + 16) * 2 + grp] = dz1[0];
        zs[(r0 + 24) * 2 + grp] = dz1[2];
    }
    if (grp == 1) {
        #pragma unroll
        for (int nt = 0; nt < 8; nt++) {
            int cc = nt * 8 + t2;
            *(float2*)(red + (r0)      * 66 + cc) = make_float2(d0[nt][0], d0[nt][1]);
            *(float2*)(red + (r0 + 8)  * 66 + cc) = make_float2(d0[nt][2], d0[nt][3]);
            *(float2*)(red + (r0 + 16) * 66 + cc) = make_float2(d1[nt][0], d1[nt][1]);
            *(float2*)(red + (r0 + 24) * 66 + cc) = make_float2(d1[nt][2], d1[nt][3]);
        }
    }
    __syncthreads();
    if (grp == 0) {
        float inv0 = 1.0f / (zs[(r0)      * 2] + zs[(r0)      * 2 + 1]);
        float inv1 = 1.0f / (zs[(r0 + 8)  * 2] + zs[(r0 + 8)  * 2 + 1]);
        float inv2 = 1.0f / (zs[(r0 + 16) * 2] + zs[(r0 + 16) * 2 + 1]);
        float inv3 = 1.0f / (zs[(r0 + 24) * 2] + zs[(r0 + 24) * 2 + 1]);
        int col0 = h * FF + t2;
        float* o0 = out + (size_t)(i0 + r0) * OUTF + col0;
        float* o1 = o0 + 8 * OUTF;
        float* o2 = o0 + 16 * OUTF;
        float* o3 = o0 + 24 * OUTF;
        #pragma unroll
        for (int nt = 0; nt < 8; nt++) {
            int cc = nt * 8 + t2;
            float2 p0 = *(const float2*)(red + (r0)      * 66 + cc);
            float2 p1 = *(const float2*)(red + (r0 + 8)  * 66 + cc);
            float2 p2 = *(const float2*)(red + (r0 + 16) * 66 + cc);
            float2 p3 = *(const float2*)(red + (r0 + 24) * 66 + cc);
            *(float2*)(o0 + nt * 8) = make_float2((d0[nt][0] + p0.x) * inv0,
                                                  (d0[nt][1] + p0.y) * inv0);
            *(float2*)(o1 + nt * 8) = make_float2((d0[nt][2] + p1.x) * inv1,
                                                  (d0[nt][3] + p1.y) * inv1);
            *(float2*)(o2 + nt * 8) = make_float2((d1[nt][0] + p2.x) * inv2,
                                                  (d1[nt][1] + p2.y) * inv2);
            *(float2*)(o3 + nt * 8) = make_float2((d1[nt][2] + p3.x) * inv3,
                                                  (d1[nt][3] + p3.y) * inv3);
        }
    }
}

// ============================================================
extern "C" void kernel_launch(void* const* d_in, const int* in_sizes, int n_in,
                              void* d_out, int out_size) {
    const float* x   = (const float*)d_in[0];
    const int*   adj = (const int*)d_in[1];
    const float* W   = (const float*)d_in[2];
    const float* aw  = (const float*)d_in[3];
    float* out = (float*)d_out;

    cudaFuncSetAttribute(gemm_tc, cudaFuncAttributeMaxDynamicSharedMemorySize, GEMM_SMEM);
    cudaFuncSetAttribute(gat_tc, cudaFuncAttributeMaxDynamicSharedMemorySize, SMEM_TC);

    prep_kernel<<<224, 256>>>(x, W);                          // launch 0
    gemm_tc<<<dim3(NN / 64, HH), 128, GEMM_SMEM>>>(aw);       // launch 1
    rowc_kernel<<<NN, 256>>>(adj);                            // launch 2
    gat_tc<<<(NN / MI) * HH, 192, SMEM_TC>>>(out);            // launch 3 (profiled)
}

// round 17
// speedup vs baseline: 1.0943x; 1.0943x over previous
#include <cuda_runtime.h>
#include <cuda_fp16.h>
#include <cstdint>

#define NN    3072
#define HH    8
#define FF    64
#define OUTF  512
#define INF_  256
#define KT    64
#define NT    (NN / KT)     // 48
#define MI    96            // i rows per CTA in gat_tc (16 rows/warp x 6 warps)
#define NW    (NN / 32)     // adj bitmask words per row
#define LOG2E 1.4426950408889634f
#define TOPK  32

// ---- scratch (device globals) ----
__device__ float d_sl[NN * HH];           // pre-scaled by log2(e)
__device__ float d_sr[NN * HH];           // pre-scaled
__device__ uint32_t d_adjbits[NN * NW];
__device__ int   d_any[NN];               // row has any adj==0
__device__ int   d_topidx[HH * TOPK];     // per-head top-K j indices (desc)
__device__ float d_topval[HH * TOPK];     // corresponding s_r values
__device__ __half d_gthi[HH * FF * NN];   // g^T fp16 (rn), j-permuted: [h][f][j']
__device__ __half d_xphi[NN * INF_];      // x split hi, k-permuted
__device__ __half d_xplo[NN * INF_];
__device__ __half d_wthi[OUTF * INF_];    // W^T split hi, k-permuted: [n][k']
__device__ __half d_wtlo[OUTF * INF_];

// permutation within 16-group: position p holds actual k = KTAB(p)
#define KTAB(pp) (2 * ((pp) >> 2) + (((pp) & 2) ? 8 : 0) + ((pp) & 1))

// select LUT: 2 mask bits -> byte_perm selector (e bytes 0-3, C bytes 4-7)
static constexpr uint64_t SELLUT = 0x3210325476107654ull;

// ---------------- helpers ----------------
__device__ __forceinline__ uint32_t smem_u32(const void* p) {
    uint32_t a;
    asm("{ .reg .u64 t; cvta.to.shared.u64 t, %1; cvt.u32.u64 %0, t; }" : "=r"(a) : "l"(p));
    return a;
}
__device__ __forceinline__ void cp16(void* dst, const void* src) {
    asm volatile("cp.async.cg.shared.global [%0], [%1], 16;\n" :: "r"(smem_u32(dst)), "l"(src));
}
__device__ __forceinline__ void cp4(void* dst, const void* src) {
    asm volatile("cp.async.ca.shared.global [%0], [%1], 4;\n" :: "r"(smem_u32(dst)), "l"(src));
}
#define CP_COMMIT() asm volatile("cp.async.commit_group;\n")
#define CP_WAIT(n)  asm volatile("cp.async.wait_group %0;\n" :: "n"(n))

__device__ __forceinline__ void mma16816(float* d, const uint32_t* a,
                                         uint32_t b0, uint32_t b1) {
    asm volatile(
        "mma.sync.aligned.m16n8k16.row.col.f32.f16.f16.f32 "
        "{%0,%1,%2,%3}, {%4,%5,%6,%7}, {%8,%9}, {%0,%1,%2,%3};"
        : "+f"(d[0]), "+f"(d[1]), "+f"(d[2]), "+f"(d[3])
        : "r"(a[0]), "r"(a[1]), "r"(a[2]), "r"(a[3]), "r"(b0), "r"(b1));
}
__device__ __forceinline__ uint32_t ph2(float lo, float hi) {
    __half2 h = __floats2half2_rn(lo, hi);
    return *(uint32_t*)&h;
}
__device__ __forceinline__ uint32_t ex2h2(uint32_t a) {
    uint32_t r;
    asm("ex2.approx.f16x2 %0, %1;" : "=r"(r) : "r"(a));
    return r;
}
__device__ __forceinline__ void split16(const float* v_strided, int stride,
                                        uint4* hi2, uint4* lo2) {
    uint32_t hw[8], lw[8];
    #pragma unroll
    for (int q = 0; q < 8; q++) {
        float v0 = v_strided[KTAB(2 * q) * stride];
        float v1 = v_strided[KTAB(2 * q + 1) * stride];
        __half h0 = __float2half_rn(v0), h1 = __float2half_rn(v1);
        float r0 = v0 - __half2float(h0), r1 = v1 - __half2float(h1);
        __half l0 = __float2half_rn(r0), l1 = __float2half_rn(r1);
        hw[q] = ((uint32_t)__half_as_ushort(h1) << 16) | __half_as_ushort(h0);
        lw[q] = ((uint32_t)__half_as_ushort(l1) << 16) | __half_as_ushort(l0);
    }
    hi2[0] = make_uint4(hw[0], hw[1], hw[2], hw[3]);
    hi2[1] = make_uint4(hw[4], hw[5], hw[6], hw[7]);
    lo2[0] = make_uint4(lw[0], lw[1], lw[2], lw[3]);
    lo2[1] = make_uint4(lw[4], lw[5], lw[6], lw[7]);
}

// ============================================================
// Kernel 0: prep = xsplit (0..191) + wsplit (192..223) +
//           adj pack + any0 (224..3295, one row per block)
// ============================================================
__global__ void prep_kernel(const float* __restrict__ x, const float* __restrict__ W,
                            const int* __restrict__ adj) {
    int t = threadIdx.x;
    if (blockIdx.x < 192) {
        __shared__ float s[16][257];
        int r0 = blockIdx.x * 16;
        #pragma unroll
        for (int q = 0; q < 4; q++) {
            int idx = t + q * 256;
            int r = idx >> 6, c4 = (idx & 63) * 4;
            float4 v = *(const float4*)(x + (size_t)(r0 + r) * INF_ + c4);
            s[r][c4] = v.x; s[r][c4 + 1] = v.y; s[r][c4 + 2] = v.z; s[r][c4 + 3] = v.w;
        }
        __syncthreads();
        int r = t >> 4, grp = (t & 15) * 16;
        uint4 hi2[2], lo2[2];
        split16(&s[r][grp], 1, hi2, lo2);
        uint4* dh = (uint4*)(d_xphi + (size_t)(r0 + r) * INF_ + grp);
        uint4* dl = (uint4*)(d_xplo + (size_t)(r0 + r) * INF_ + grp);
        dh[0] = hi2[0]; dh[1] = hi2[1];
        dl[0] = lo2[0]; dl[1] = lo2[1];
    } else if (blockIdx.x < 224) {
        __shared__ float s[64][65];
        int b = blockIdx.x - 192;
        int k0 = (b & 3) * 64, n0 = (b >> 2) * 64;
        #pragma unroll
        for (int q = 0; q < 4; q++) {
            int idx = t + q * 256;
            int k = idx >> 4, n4 = (idx & 15) * 4;
            float4 v = *(const float4*)(W + (size_t)(k0 + k) * OUTF + n0 + n4);
            s[k][n4] = v.x; s[k][n4 + 1] = v.y; s[k][n4 + 2] = v.z; s[k][n4 + 3] = v.w;
        }
        __syncthreads();
        int n = t >> 2, grp = (t & 3) * 16;
        uint4 hi2[2], lo2[2];
        split16(&s[grp][n], 65, hi2, lo2);
        uint4* dh = (uint4*)(d_wthi + (size_t)(n0 + n) * INF_ + k0 + grp);
        uint4* dl = (uint4*)(d_wtlo + (size_t)(n0 + n) * INF_ + k0 + grp);
        dh[0] = hi2[0]; dh[1] = hi2[1];
        dl[0] = lo2[0]; dl[1] = lo2[1];
    } else {
        // adj -> bitmask + any0 (one row per block, R13-proven ballot loop)
        __shared__ int cnts[8];
        int i = blockIdx.x - 224;
        const int* ar = adj + (size_t)i * NN;
        int pc = 0;
        for (int j = t; j < NN; j += 256) {
            uint32_t bal = __ballot_sync(0xffffffffu, ar[j] != 0);
            if ((t & 31) == 0) { d_adjbits[i * NW + (j >> 5)] = bal; pc += __popc(bal); }
        }
        if ((t & 31) == 0) cnts[t >> 5] = pc;
        __syncthreads();
        if (t == 0) {
            int s = 0;
            #pragma unroll
            for (int q = 0; q < 8; q++) s += cnts[q];
            d_any[i] = (s < NN);
        }
    }
}

// ============================================================
// Kernel 1: g = x @ W via HMMA (3-pass split), fused epilogue:
// scores (scaled) + g^T fp16 j-permuted. grid (48, 8), 128 thr.
// ============================================================
constexpr int BROW = 264;
constexpr int GEMM_SMEM = 2 * 64 * BROW * 2;    // 67584 B

__global__ void __launch_bounds__(128, 1) gemm_tc(const float* __restrict__ aw) {
    extern __shared__ char gsm[];
    __half* Bhi = (__half*)gsm;
    __half* Blo = Bhi + 64 * BROW;
    int t = threadIdx.x, lane = t & 31, w = t >> 5;
    int m0 = blockIdx.x * 64, h = blockIdx.y, n0 = h * FF;

    #pragma unroll
    for (int q = 0; q < 16; q++) {
        int idx = t + q * 128;
        int n = idx >> 5, c = idx & 31;
        cp16(Bhi + n * BROW + c * 8, d_wthi + (size_t)(n0 + n) * INF_ + c * 8);
        cp16(Blo + n * BROW + c * 8, d_wtlo + (size_t)(n0 + n) * INF_ + c * 8);
    }
    CP_COMMIT(); CP_WAIT(0);
    __syncthreads();

    int gid = lane >> 2, tig = lane & 3;
    const uint2* xh0 = (const uint2*)(d_xphi + (size_t)(m0 + w * 16 + gid) * INF_);
    const uint2* xh8 = (const uint2*)(d_xphi + (size_t)(m0 + w * 16 + gid + 8) * INF_);
    const uint2* xl0 = (const uint2*)(d_xplo + (size_t)(m0 + w * 16 + gid) * INF_);
    const uint2* xl8 = (const uint2*)(d_xplo + (size_t)(m0 + w * 16 + gid + 8) * INF_);

    float d[8][4] = {};
    #pragma unroll 4
    for (int s = 0; s < 16; s++) {
        uint2 ah0 = xh0[s * 4 + tig], ah8 = xh8[s * 4 + tig];
        uint2 al0 = xl0[s * 4 + tig], al8 = xl8[s * 4 + tig];
        uint32_t Ahi[4] = {ah0.x, ah8.x, ah0.y, ah8.y};
        uint32_t Alo[4] = {al0.x, al8.x, al0.y, al8.y};
        #pragma unroll
        for (int nt = 0; nt < 8; nt++) {
            int boff = (nt * 8 + gid) * BROW + s * 16 + 4 * tig;
            uint2 bh = *(const uint2*)(Bhi + boff);
            uint2 bl = *(const uint2*)(Blo + boff);
            mma16816(d[nt], Ahi, bh.x, bh.y);
            mma16816(d[nt], Ahi, bl.x, bl.y);
            mma16816(d[nt], Alo, bh.x, bh.y);
        }
    }
    __syncthreads();    // B dead; overlay transpose buffer

    float* trans = (float*)gsm;     // [64][66]
    int r1 = w * 16 + gid, r2 = r1 + 8;
    #pragma unroll
    for (int nt = 0; nt < 8; nt++) {
        int cc = nt * 8 + 2 * tig;
        trans[r1 * 66 + cc] = d[nt][0]; trans[r1 * 66 + cc + 1] = d[nt][1];
        trans[r2 * 66 + cc] = d[nt][2]; trans[r2 * 66 + cc + 1] = d[nt][3];
    }
    __syncthreads();

    // ---- fused scores (x log2e) ----
    {
        int r = t >> 1, half = t & 1;
        const float* row = trans + r * 66 + half * 32;
        const float* awl = aw + half * 32;
        const float* awr = aw + 64 + half * 32;
        float sl = 0.f, sr = 0.f;
        #pragma unroll
        for (int q = 0; q < 32; q++) {
            float gv = row[q];
            sl += gv * awl[q];
            sr += gv * awr[q];
        }
        sl += __shfl_xor_sync(0xffffffffu, sl, 1);
        sr += __shfl_xor_sync(0xffffffffu, sr, 1);
        if (!half) {
            d_sl[(m0 + r) * HH + h] = sl * LOG2E;
            d_sr[(m0 + r) * HH + h] = sr * LOG2E;
        }
    }

    // ---- g^T fp16 (hi only), j-permuted ----
    {
        int f = t >> 1, half = t & 1;
        #pragma unroll
        for (int jq = 0; jq < 2; jq++) {
            int p0 = 32 * half + jq * 16;
            uint32_t hw[8];
            #pragma unroll
            for (int q = 0; q < 8; q++) {
                float v0 = trans[(p0 + KTAB(2 * q)) * 66 + f];
                float v1 = trans[(p0 + KTAB(2 * q + 1)) * 66 + f];
                hw[q] = ph2(v0, v1);
            }
            uint4* dh = (uint4*)(d_gthi + ((size_t)h * FF + f) * NN + m0 + p0);
            dh[0] = make_uint4(hw[0], hw[1], hw[2], hw[3]);
            dh[1] = make_uint4(hw[4], hw[5], hw[6], hw[7]);
        }
    }
}

// ============================================================
// Kernel 2: topk -- per head, top-32 s_r values + indices (desc).
// 8 CTAs x 256 thr, smem-resident column.
// ============================================================
__global__ void topk_kernel() {
    __shared__ float vals[NN];
    __shared__ float wm[8];
    __shared__ int   wi[8];
    int h = blockIdx.x, t = threadIdx.x, lane = t & 31, w = t >> 5;
    #pragma unroll
    for (int q = 0; q < NN / 256; q++)
        vals[t + q * 256] = d_sr[(size_t)(t + q * 256) * HH + h];
    __syncthreads();
    for (int k = 0; k < TOPK; k++) {
        float bm = -3.0e38f; int bi = 0;
        #pragma unroll
        for (int q = 0; q < NN / 256; q++) {
            float v = vals[t + q * 256];
            if (v > bm) { bm = v; bi = t + q * 256; }
        }
        #pragma unroll
        for (int o = 16; o; o >>= 1) {
            float om = __shfl_down_sync(0xffffffffu, bm, o);
            int   oi = __shfl_down_sync(0xffffffffu, bi, o);
            if (om > bm) { bm = om; bi = oi; }
        }
        if (lane == 0) { wm[w] = bm; wi[w] = bi; }
        __syncthreads();
        if (t == 0) {
            float fm = wm[0]; int fi = wi[0];
            #pragma unroll
            for (int q = 1; q < 8; q++) if (wm[q] > fm) { fm = wm[q]; fi = wi[q]; }
            d_topval[h * TOPK + k] = fm;
            d_topidx[h * TOPK + k] = fi;
            vals[fi] = -3.0e38f;
        }
        __syncthreads();
    }
}

// ============================================================
// Kernel 3: HMMA main (R13 body) + fused m/C prologue via top-K probe.
// MI=96, 192 thr, 256 CTAs, 2 CTAs/SM.
// ============================================================
constexpr int BUF_BYTES = 64 * 80 * 2;              // 10240 per stage
constexpr int OFF_SR3   = 3 * BUF_BYTES;            // 30720
constexpr int OFF_MC    = OFF_SR3 + 3 * 256;        // 31488
constexpr int SMEM_TC   = OFF_MC + 2 * MI * 4;      // 32256

__global__ void __launch_bounds__(192, 2) gat_tc(float* __restrict__ out) {
    extern __shared__ char smem[];
    float* sm_m = (float*)(smem + OFF_MC);
    float* sm_C = sm_m + MI;

    int t = threadIdx.x, lane = t & 31, mt = t >> 5;   // mt 0..5
    int h = blockIdx.x & 7;
    int i0 = (blockIdx.x >> 3) * MI;
    int gid = lane >> 2, tig = lane & 3;
    int t2 = 2 * tig;
    int r0 = mt * 16 + gid;             // rows r0, r0+8

    const uint32_t* ab0 = d_adjbits + (size_t)(i0 + r0) * NW;
    const uint32_t* ab1 = ab0 + 8 * NW;

    // ---- hoisted staging descriptors (512 cp16 over 192 threads) ----
    const char* g_src[3];
    uint32_t g_dst[3];
    #pragma unroll
    for (int q = 0; q < 3; q++) {
        int idx = t + q * 192;
        if (idx < 512) {
            int f = idx >> 3, c = idx & 7;
            g_src[q] = (const char*)(d_gthi + ((size_t)h * FF + f) * NN + c * 8);
            g_dst[q] = (uint32_t)((f * 80 + c * 8) * 2);
        }
    }
    const char* s_src = nullptr;
    uint32_t s_dst = 0;
    if (t < 64) {
        int joff = (t & ~15) + KTAB(t & 15);
        s_src = (const char*)(d_sr + (size_t)joff * HH + h);
        s_dst = (uint32_t)(t * 4);
    }

    auto stage = [&](int bi) {
        uint32_t boff = bi * BUF_BYTES;
        cp16(smem + boff + g_dst[0], g_src[0]); g_src[0] += 64 * 2;
        cp16(smem + boff + g_dst[1], g_src[1]); g_src[1] += 64 * 2;
        if (t < 128) { cp16(smem + boff + g_dst[2], g_src[2]); g_src[2] += 64 * 2; }
        if (t < 64) {
            cp4(smem + OFF_SR3 + bi * 256 + s_dst, s_src);
            s_src += 64 * HH * 4;         // +64 j (floats, stride HH)
        }
    };

    stage(0); CP_COMMIT();
    stage(1); CP_COMMIT();

    // ---- prologue: m, C per row via top-K probe (exact masked max) ----
    if (t < MI) {
        int i = i0 + t;
        const uint32_t* bwr = d_adjbits + (size_t)i * NW;
        float mrad = -3.0e38f;
        for (int k = 0; k < TOPK; k++) {
            int j = d_topidx[h * TOPK + k];
            uint32_t wv = bwr[j >> 5];
            if ((wv >> (j & 31)) & 1u) { mrad = d_topval[h * TOPK + k]; break; }
        }
        if (mrad < -1.0e38f) {           // fallback: P ~ 2^-32 per pair
            for (int q2 = 0; q2 < NW; q2++) {
                uint32_t wv = bwr[q2];
                while (wv) {
                    int bpos = __ffs(wv) - 1; wv &= wv - 1;
                    mrad = fmaxf(mrad, d_sr[(size_t)(q2 * 32 + bpos) * HH + h]);
                }
            }
        }
        int any0 = d_any[i];
        float sl = d_sl[i * HH + h];
        float s  = sl + mrad;
        float lk = fmaxf(s, 0.2f * s);
        float m  = any0 ? fmaxf(LOG2E, lk) : lk;
        sm_m[t] = m;
        sm_C[t] = any0 ? exp2f(LOG2E - m) : 0.0f;
    }
    __syncthreads();

    // per-row constants from prologue
    int gi0 = (i0 + r0) * HH + h;
    int gi1 = gi0 + 8 * HH;
    float mA = sm_m[r0], mB = sm_m[r0 + 8];
    float slmA = d_sl[gi0] - mA, slmB = d_sl[gi1] - mB;
    float cmA = -0.8f * mA, cmB = -0.8f * mB;
    uint32_t CA2 = ph2(sm_C[r0], sm_C[r0]);
    uint32_t CB2 = ph2(sm_C[r0 + 8], sm_C[r0 + 8]);

    float d[8][4] = {};
    float dz[4] = {};
    uint32_t bz = (gid == 0) ? 0x3C003C00u : 0u;   // ones column (n=0)
    int cur = 0, stg = 2;

    for (int jt = 0; jt < NT; ++jt) {
        if (jt < NT - 1) CP_WAIT(1); else CP_WAIT(0);
        __syncthreads();
        if (jt + 2 < NT) { stage(stg); CP_COMMIT(); stg = (stg == 2) ? 0 : stg + 1; }

        uint2 bw0 = *(const uint2*)(ab0 + jt * 2);
        uint2 bw1 = *(const uint2*)(ab1 + jt * 2);
        const float* srh = (const float*)(smem + OFF_SR3 + cur * 256);

        uint32_t A[4][4];
        #pragma unroll
        for (int s = 0; s < 4; s++) {
            float4 sv = *(const float4*)(srh + s * 16 + 4 * tig);
            uint32_t shA = ((s < 2) ? bw0.x : bw0.y) >> (((s & 1) << 4) + t2);
            uint32_t shB = ((s < 2) ? bw1.x : bw1.y) >> (((s & 1) << 4) + t2);
            // row r0
            {
                float u0 = sv.x + slmA, u1 = sv.y + slmA;
                float u2 = sv.z + slmA, u3 = sv.w + slmA;
                float l0 = fmaxf(u0, fmaf(u0, 0.2f, cmA));
                float l1 = fmaxf(u1, fmaf(u1, 0.2f, cmA));
                float l2 = fmaxf(u2, fmaf(u2, 0.2f, cmA));
                float l3 = fmaxf(u3, fmaf(u3, 0.2f, cmA));
                uint32_t e01 = ex2h2(ph2(l0, l1));
                uint32_t e23 = ex2h2(ph2(l2, l3));
                uint32_t sel1 = (uint32_t)(SELLUT >> ((shA << 4) & 0x30));
                uint32_t sel2 = (uint32_t)(SELLUT >> ((shA >> 4) & 0x30));
                A[s][0] = __byte_perm(e01, CA2, sel1);
                A[s][2] = __byte_perm(e23, CA2, sel2);
            }
            // row r0+8
            {
                float u0 = sv.x + slmB, u1 = sv.y + slmB;
                float u2 = sv.z + slmB, u3 = sv.w + slmB;
                float l0 = fmaxf(u0, fmaf(u0, 0.2f, cmB));
                float l1 = fmaxf(u1, fmaf(u1, 0.2f, cmB));
                float l2 = fmaxf(u2, fmaf(u2, 0.2f, cmB));
                float l3 = fmaxf(u3, fmaf(u3, 0.2f, cmB));
                uint32_t e01 = ex2h2(ph2(l0, l1));
                uint32_t e23 = ex2h2(ph2(l2, l3));
                uint32_t sel1 = (uint32_t)(SELLUT >> ((shB << 4) & 0x30));
                uint32_t sel2 = (uint32_t)(SELLUT >> ((shB >> 4) & 0x30));
                A[s][1] = __byte_perm(e01, CB2, sel1);
                A[s][3] = __byte_perm(e23, CB2, sel2);
            }
            mma16816(dz, A[s], bz, bz);     // z accumulation on tensor pipe
        }

        const __half* bb = (const __half*)(smem + cur * BUF_BYTES);
        #pragma unroll
        for (int s = 0; s < 4; s++) {
            #pragma unroll
            for (int nt = 0; nt < 8; nt++) {
                uint2 b = *(const uint2*)(bb + (nt * 8 + gid) * 80 + s * 16 + 4 * tig);
                mma16816(d[nt], A[s], b.x, b.y);
            }
        }
        cur = (cur == 2) ? 0 : cur + 1;
    }

    // ---- epilogue: z lives in dz[0]/dz[2] of tig==0 lanes ----
    float zA = __shfl_sync(0xffffffffu, dz[0], lane & ~3);
    float zB = __shfl_sync(0xffffffffu, dz[2], lane & ~3);
    float inv0 = 1.0f / zA;
    float inv1 = 1.0f / zB;
    int col0 = h * FF + 2 * tig;
    float* o0 = out + (size_t)(i0 + r0) * OUTF + col0;
    float* o1 = out + (size_t)(i0 + r0 + 8) * OUTF + col0;
    #pragma unroll
    for (int nt = 0; nt < 8; nt++) {
        *(float2*)(o0 + nt * 8) = make_float2(d[nt][0] * inv0, d[nt][1] * inv0);
        *(float2*)(o1 + nt * 8) = make_float2(d[nt][2] * inv1, d[nt][3] * inv1);
    }
}

// ============================================================
extern "C" void kernel_launch(void* const* d_in, const int* in_sizes, int n_in,
                              void* d_out, int out_size) {
    const float* x   = (const float*)d_in[0];
    const int*   adj = (const int*)d_in[1];
    const float* W   = (const float*)d_in[2];
    const float* aw  = (const float*)d_in[3];
    float* out = (float*)d_out;

    cudaFuncSetAttribute(gemm_tc, cudaFuncAttributeMaxDynamicSharedMemorySize, GEMM_SMEM);
    cudaFuncSetAttribute(gat_tc, cudaFuncAttributeMaxDynamicSharedMemorySize, SMEM_TC);

    prep_kernel<<<224 + NN, 256>>>(x, W, adj);                // launch 0
    gemm_tc<<<dim3(NN / 64, HH), 128, GEMM_SMEM>>>(aw);       // launch 1
    topk_kernel<<<HH, 256>>>();                               // launch 2
    gat_tc<<<(NN / MI) * HH, 192, SMEM_TC>>>(out);            // launch 3 (profiled)
}